// round 17
// baseline (speedup 1.0000x reference)
#include <cuda_runtime.h>
#include <cuda.h>
#include <cstdint>

#define NS       8192
#define NC       1024
#define NK       4
#define TILE     32            // channels per block tile
#define THREADS  128           // samples per block (1 per thread)
#define PAD      4
#define NW       40            // words per logical window row (covers w=0..37 + pad)
#define WIN_WORDS (32 * (NW / 2))   // 32 banks x 20 depth = 640 words

__global__ void __launch_bounds__(THREADS)
smf_kernel(const float* __restrict__ comp,      // [4, 1024]
           const float* __restrict__ contrib,   // [8192, 4]
           const float* __restrict__ shift,     // [8192, 4]
           const __grid_constant__ CUtensorMap tmap)   // out [8192, 1024] f32, SW128
{
    // bank-partitioned window: row (c,k) -> bank group {2G, 2G+1}, G = 4c+k
    // addr(G, w) = 2G + (w&1) + 32*(w>>1);  word w of copy c = comp[k, c0-4+c+w]
    __shared__ __align__(16)   float swin[WIN_WORDS];
    __shared__ __align__(1024) float st[THREADS * TILE];   // 16KB SW128 staging tile

    const int tid  = threadIdx.x;
    const int tile = blockIdx.x & 31;           // 32 channel tiles
    const int grp  = blockIdx.x >> 5;           // 64 sample groups
    const int c0   = tile * TILE;
    const int s0   = grp * THREADS;

    // prefetch per-sample params (hide LDG latency under window fill)
    const float4 sh4 = __ldg((const float4*)(shift   + (size_t)(s0 + tid) * NK));
    const float4 cn4 = __ldg((const float4*)(contrib + (size_t)(s0 + tid) * NK));

    // ---- fill window (consecutive tids -> consecutive banks, conflict-free) ----
    #pragma unroll
    for (int idx = tid; idx < WIN_WORDS; idx += THREADS) {   // 5 iterations
        const int G = (idx >> 1) & 15;
        const int c = G >> 2, k = G & 3;
        const int w = ((idx >> 5) << 1) | (idx & 1);
        const int j = c0 - PAD + c + w;
        swin[idx] = (j >= 0 && j < NC) ? comp[k * NC + j] : 0.0f;
    }

    const float shv[NK] = { sh4.x, sh4.y, sh4.z, sh4.w };
    const float cnv[NK] = { cn4.x, cn4.y, cn4.z, cn4.w };

    float a[NK], b[NK];
    const float* basep[NK];                     // smem base -> LDS [R + 128*ip]
    #pragma unroll
    for (int k = 0; k < NK; k++) {
        const float sh = shv[k];
        const float cn = cnv[k];
        int fi = (int)floorf(sh);               // in [-4, 4]
        fi = max(-4, min(3, fi));               // clamp; sh==4.0 folds into fr=1
        const float fr = sh - (float)fi;
        b[k] = cn * fr;                         // weight of tap fi+1
        a[k] = cn - b[k];                       // cn*(1-fr)
        const int c = (fi + 4) & 3;             // copy -> even w0 = fi+4-c in {0,4}
        const int m = (fi + 4) >> 2;            // 0 or 1
        basep[k] = swin + (2 * (4 * c + k) + 64 * m);
    }
    __syncthreads();

    // ---- main: per 2 channels per k: 1 LDS.64 (stride 128B, imm offset) + 4 FFMA ----
    float2 u[NK];
    #pragma unroll
    for (int k = 0; k < NK; k++) u[k] = *(const float2*)basep[k];

    float4* st4 = (float4*)st;
    const int xorl = tid & 7;                   // SW128 column xor for this row
    float4 buf;
    #pragma unroll
    for (int ip = 0; ip < TILE / 2; ip++) {     // channels 2ip, 2ip+1
        float a0 = 0.f, a1 = 0.f;
        #pragma unroll
        for (int k = 0; k < NK; k++) {
            const float2 v = *(const float2*)(basep[k] + 32 * (ip + 1));
            a0 += a[k] * u[k].x + b[k] * u[k].y;
            a1 += a[k] * u[k].y + b[k] * v.x;
            u[k] = v;
        }
        if (ip & 1) {                            // SW128-swizzled STS.128, conflict-free
            buf.z = a0; buf.w = a1;
            st4[tid * 8 + ((ip >> 1) ^ xorl)] = buf;
        } else { buf.x = a0; buf.y = a1; }
    }

    // ---- one TMA tensor store for the whole [128 x 32] tile ----
    asm volatile("fence.proxy.async.shared::cta;" ::: "memory");
    __syncthreads();
    if (tid == 0) {
        const uint32_t st_u32 = (uint32_t)__cvta_generic_to_shared(st);
        asm volatile(
            "cp.async.bulk.tensor.2d.global.shared::cta.tile.bulk_group "
            "[%0, {%1, %2}], [%3];"
            :: "l"(&tmap), "r"(c0), "r"(s0), "r"(st_u32)
            : "memory");
        asm volatile("cp.async.bulk.commit_group;" ::: "memory");
        asm volatile("cp.async.bulk.wait_group 0;" ::: "memory");
    }
}

// ---- host: tensormap via runtime driver-entry-point (no -lcuda link) ----
typedef CUresult (*PFN_encodeTiled)(
    CUtensorMap*, CUtensorMapDataType, cuuint32_t, void*,
    const cuuint64_t*, const cuuint64_t*, const cuuint32_t*, const cuuint32_t*,
    CUtensorMapInterleave, CUtensorMapSwizzle, CUtensorMapL2promotion,
    CUtensorMapFloatOOBfill);

static PFN_encodeTiled get_encoder()
{
    static PFN_encodeTiled fn = nullptr;
    if (!fn) {
        void* p = nullptr;
        cudaDriverEntryPointQueryResult qr;
#if CUDART_VERSION >= 12050
        cudaGetDriverEntryPointByVersion("cuTensorMapEncodeTiled", &p, 12000,
                                         cudaEnableDefault, &qr);
#else
        cudaGetDriverEntryPoint("cuTensorMapEncodeTiled", &p,
                                cudaEnableDefault, &qr);
#endif
        fn = (PFN_encodeTiled)p;
    }
    return fn;
}

extern "C" void kernel_launch(void* const* d_in, const int* in_sizes, int n_in,
                              void* d_out, int out_size)
{
    // inputs [8192,1024] (ignored), components [4,1024],
    // contributions [8192,4], shift [8192,4]
    const float* comp    = (const float*)d_in[1];
    const float* contrib = (const float*)d_in[2];
    const float* shift   = (const float*)d_in[3];

    CUtensorMap tmap;
    {
        cuuint64_t dims[2]    = { NC, NS };           // inner = channels
        cuuint64_t strides[1] = { NC * sizeof(float) };
        cuuint32_t box[2]     = { TILE, THREADS };    // 32 ch x 128 samples
        cuuint32_t estr[2]    = { 1, 1 };
        get_encoder()(&tmap, CU_TENSOR_MAP_DATA_TYPE_FLOAT32, 2, d_out,
                      dims, strides, box, estr,
                      CU_TENSOR_MAP_INTERLEAVE_NONE, CU_TENSOR_MAP_SWIZZLE_128B,
                      CU_TENSOR_MAP_L2_PROMOTION_L2_128B,
                      CU_TENSOR_MAP_FLOAT_OOB_FILL_NONE);
    }

    smf_kernel<<<32 * (NS / THREADS), THREADS>>>(comp, contrib, shift, tmap);  // 2048
}